// round 10
// baseline (speedup 1.0000x reference)
#include <cuda_runtime.h>
#include <math.h>

#define T_DIM 512
#define B_DIM 32
#define V_DIM 4096
#define S_DIM 64
#define L_DIM 129
#define PRESCALE 14.0f         // probs stored as p * 2^14

#define LOG2E 1.4426950408889634f
#define LN2   0.6931471805599453f

// Scratch (zero-init at load; g_done reset in-kernel each run).
__device__ float g_pb[(size_t)B_DIM * T_DIM];        // blank probs
__device__ float g_pr[(size_t)B_DIM * T_DIM * 64];   // label probs (label order)
__device__ float g_nll[B_DIM];
__device__ int   g_done;

__device__ __forceinline__ float ex2(float x) {
    float y; asm("ex2.approx.f32 %0, %1;" : "=f"(y) : "f"(x)); return y;
}
__device__ __forceinline__ float lg2(float x) {
    float y; asm("lg2.approx.f32 %0, %1;" : "=f"(y) : "f"(x)); return y;
}
__device__ __forceinline__ unsigned warp_max_u32(unsigned v) {
    unsigned r;
    asm("redux.sync.max.u32 %0, %1, 0xffffffff;" : "=r"(r) : "r"(v));
    return r;
}

// ---------------------------------------------------------------------------
// Kernel 1: per (t,b) row: one-pass sum(exp) + gather 65 prescaled probs.
// Rows with t >= input_len[b] skipped (~25% DRAM). Writes split layout:
// g_pb (blank) + g_pr (64 label probs, label order -> pairable by lane).
// ---------------------------------------------------------------------------
__global__ __launch_bounds__(256) void k_lse_gather(
    const float* __restrict__ acts, const int* __restrict__ labels,
    const int* __restrict__ input_len) {
    const int row = blockIdx.x;            // t*B + b
    const int t   = row / B_DIM;
    const int b   = row - t * B_DIM;
    if (t >= __ldg(&input_len[b])) return; // dead row

    const float* __restrict__ x = acts + (size_t)row * V_DIM;
    const int tid = threadIdx.x;

    const float4* __restrict__ x4 = reinterpret_cast<const float4*>(x);
    float s = 0.0f;
    #pragma unroll
    for (int k = 0; k < 4; ++k) {
        float4 r = __ldcs(&x4[tid + 256 * k]);   // stream, evict-first
        s += ex2(r.x * LOG2E) + ex2(r.y * LOG2E)
           + ex2(r.z * LOG2E) + ex2(r.w * LOG2E);
    }

    __shared__ float s_s[8];
    __shared__ float s_bcast;
    #pragma unroll
    for (int o = 16; o; o >>= 1) s += __shfl_xor_sync(0xffffffffu, s, o);
    if ((tid & 31) == 0) s_s[tid >> 5] = s;
    __syncthreads();
    if (tid < 32) {
        float v = (tid < 8) ? s_s[tid] : 0.0f;
        #pragma unroll
        for (int o = 4; o; o >>= 1) v += __shfl_xor_sync(0xffffffffu, v, o);
        if (tid == 0) s_bcast = lg2(v);
    }
    __syncthreads();
    const float log2sum = s_bcast;

    if (tid < 64) {
        const int cls = __ldg(&labels[b * S_DIM + tid]);
        g_pr[((size_t)b * T_DIM + t) * 64 + tid] =
            ex2(x[cls] * LOG2E - log2sum + PRESCALE);
    }
    if (tid == 64)
        g_pb[(size_t)b * T_DIM + t] = ex2(x[0] * LOG2E - log2sum + PRESCALE);
}

// ---------------------------------------------------------------------------
// Kernel 2: scaled linear-domain CTC alpha, one block per batch.
// Conflict-free LDS (blank broadcast + one float2 per lane), pipelined shfl,
// deferred redux renorm (period 4, consumed one group later -> latency
// hidden). Last block reduces the 32 NLLs into out[0].
// ---------------------------------------------------------------------------
__global__ __launch_bounds__(128) void k_alpha(
    const int* __restrict__ labels,
    const int* __restrict__ input_len,
    const int* __restrict__ target_len,
    float* __restrict__ out) {
    extern __shared__ float sm[];
    float*  s_pb = sm;                               // 520 floats (pad)
    float2* s_pr = reinterpret_cast<float2*>(sm + 520);  // (T+4)*32 float2
    const int b   = blockIdx.x;
    const int tid = threadIdx.x;
    const int len = __ldg(&input_len[b]);

    // Cooperative preload of live rows.
    {
        const float4* __restrict__ srcb =
            reinterpret_cast<const float4*>(g_pb + (size_t)b * T_DIM);
        float4* dstb = reinterpret_cast<float4*>(s_pb);
        for (int i = tid; i < (len + 3) >> 2; i += 128) dstb[i] = srcb[i];
        const float4* __restrict__ srcp =
            reinterpret_cast<const float4*>(g_pr + (size_t)b * T_DIM * 64);
        float4* dstp = reinterpret_cast<float4*>(s_pr);
        const int n4 = len * 16;                     // 64 floats/row / 4
        #pragma unroll 4
        for (int i = tid; i < n4; i += 128) dstp[i] = srcp[i];
    }
    __syncthreads();

    if (tid < 32) {
        const int lane = tid;
        const int* lab = labels + b * S_DIM;
        const float m0   = (lane == 0) ? 0.0f : 1.0f;
        const float sk1f = ((lane >= 1) &&
            (__ldg(&lab[2 * lane]) != __ldg(&lab[2 * lane - 1]))) ? 1.0f : 0.0f;
        const float sk3f =
            (__ldg(&lab[2 * lane + 1]) != __ldg(&lab[2 * lane])) ? 1.0f : 0.0f;

        const float2* __restrict__ prl = s_pr + lane;    // lane's pair column

        float a0 = (lane == 0) ? s_pb[0] : 0.0f;
        float a1 = (lane == 0) ? prl[0].x : 0.0f;
        float a2 = 0.0f, a3 = 0.0f, a4 = 0.0f;
        float p3 = 0.0f;
        float s01 = a0 + a1;
        float s23 = 0.0f;
        int   E  = 0;

        auto step = [&](float pb, float2 pr) {
            const float n3 = fmaf(a1, sk3f, s23) * pr.y;
            const float t3 = __shfl_up_sync(0xffffffffu, n3, 1);
            const float n0 = fmaf(p3, m0, a0) * pb;
            const float n1 = fmaf(p3, sk1f, s01) * pr.x;
            const float n2 = (a2 + a1) * pb;
            a4 = (a4 + a3) * pb;          // real only on lane31; junk benign
            s01 = n0 + n1;
            s23 = n2 + n3;
            a0 = n0; a1 = n1; a2 = n2; a3 = n3;
            p3 = t3;                      // lane0 junk masked by m0/sk1f
        };

        const int nsteps = len - 1;
        const int ngr    = nsteps >> 2;              // groups of 4 steps
        int t = 1;

        // 2-row named-register prefetch pipeline.
        float  pb0 = s_pb[1],        pb1 = s_pb[2];
        float2 pr0 = prl[1 * 32],    pr1 = prl[2 * 32];

        unsigned pend = 0x3f800000u;                 // bits(1.0f): identity
        #pragma unroll 1
        for (int g = 0; g < ngr; ++g) {
            #pragma unroll
            for (int u = 0; u < 2; ++u) {            // 2 units x 2 steps
                const float  npb0 = s_pb[t + 2],     npb1 = s_pb[t + 3];
                const float2 npr0 = prl[(t + 2) * 32], npr1 = prl[(t + 3) * 32];
                step(pb0, pr0);
                step(pb1, pr1);
                pb0 = npb0; pr0 = npr0;
                pb1 = npb1; pr1 = npr1;
                t += 2;
            }
            // Consume redux issued LAST group (latency hidden), apply scale.
            const int e = (int)(pend >> 23);
            E += e - 127;
            const float sc = __uint_as_float((unsigned)(254 - e) << 23);
            a0 *= sc; a1 *= sc; a2 *= sc; a3 *= sc; a4 *= sc;
            p3 *= sc; s01 *= sc; s23 *= sc;
            // Issue redux on post-apply magnitudes; consumed next group.
            float m = fmaxf(fmaxf(a0, a1), fmaxf(fmaxf(a2, a3), a4));
            pend = warp_max_u32(__float_as_uint(m));
        }
        #pragma unroll 1
        for (; t < len; ++t)                          // <=3 tail steps
            step(s_pb[t], prl[t * 32]);
        // (pending redux intentionally dropped: E only counts applied scales)

        // Stash alphas in smem (slab no longer needed) and finalize.
        __syncwarp();
        s_pb[4 * lane + 0] = a0;
        s_pb[4 * lane + 1] = a1;
        s_pb[4 * lane + 2] = a2;
        s_pb[4 * lane + 3] = a3;
        if (lane == 31) s_pb[128] = a4;
        __syncwarp();

        if (lane == 0) {
            int hi = 2 * __ldg(&target_len[b]);
            if (hi > L_DIM - 1) hi = L_DIM - 1;
            int lo = hi - 1; if (lo < 0) lo = 0;
            const float sum = s_pb[hi] + s_pb[lo];
            float v = -(lg2(sum) + (float)E - PRESCALE * (float)len) * LN2;
            if (!isfinite(v) || v > 1e29f || sum <= 0.0f) v = 0.0f;
            g_nll[b] = v;

            __threadfence();
            const int old = atomicAdd(&g_done, 1);
            if (old == B_DIM - 1) {
                __threadfence();
                float s = 0.0f;
                #pragma unroll
                for (int i = 0; i < B_DIM; ++i)
                    s += ((volatile float*)g_nll)[i];
                out[0] = s;
                g_done = 0;
            }
        }
    }
}

extern "C" void kernel_launch(void* const* d_in, const int* in_sizes, int n_in,
                              void* d_out, int out_size) {
    const float* acts   = (const float*)d_in[0];
    const int*   labels = (const int*)d_in[1];
    const int*   ilen   = (const int*)d_in[2];
    const int*   tlen   = (const int*)d_in[3];
    (void)in_sizes; (void)n_in; (void)out_size;

    // s_pb: 520 floats; s_pr: (T+4) rows x 32 float2 (prefetch slack).
    const int smem_bytes = (520 + (T_DIM + 4) * 64) * (int)sizeof(float);
    cudaFuncSetAttribute(k_alpha, cudaFuncAttributeMaxDynamicSharedMemorySize,
                         smem_bytes);

    k_lse_gather<<<T_DIM * B_DIM, 256>>>(acts, labels, ilen);
    k_alpha<<<B_DIM, 128, smem_bytes>>>(labels, ilen, tlen, (float*)d_out);
}

// round 11
// speedup vs baseline: 1.1165x; 1.1165x over previous
#include <cuda_runtime.h>
#include <math.h>

#define T_DIM 512
#define B_DIM 32
#define V_DIM 4096
#define S_DIM 64
#define L_DIM 129
#define PRESCALE 14.0f         // probs stored as p * 2^14

#define LOG2E 1.4426950408889634f
#define LN2   0.6931471805599453f

// Scratch (zero-init at load; g_done reset in-kernel each run).
__device__ float g_pb[(size_t)B_DIM * T_DIM];        // blank probs
__device__ float g_pr[(size_t)B_DIM * T_DIM * 64];   // label probs (label order)
__device__ float g_nll[B_DIM];
__device__ int   g_done;

__device__ __forceinline__ float ex2(float x) {
    float y; asm("ex2.approx.f32 %0, %1;" : "=f"(y) : "f"(x)); return y;
}
__device__ __forceinline__ float lg2(float x) {
    float y; asm("lg2.approx.f32 %0, %1;" : "=f"(y) : "f"(x)); return y;
}
__device__ __forceinline__ unsigned warp_max_u32(unsigned v) {
    unsigned r;
    asm("redux.sync.max.u32 %0, %1, 0xffffffff;" : "=r"(r) : "r"(v));
    return r;
}

// ---------------------------------------------------------------------------
// Kernel 1: per (t,b) row: one-pass sum(exp) + gather 65 prescaled probs.
// Rows with t >= input_len[b] skipped (~25% DRAM). Split layout:
// g_pb (blank) + g_pr (64 label probs, label order -> float2 per lane).
// ---------------------------------------------------------------------------
__global__ __launch_bounds__(256) void k_lse_gather(
    const float* __restrict__ acts, const int* __restrict__ labels,
    const int* __restrict__ input_len) {
    const int row = blockIdx.x;            // t*B + b
    const int t   = row / B_DIM;
    const int b   = row - t * B_DIM;
    if (t >= __ldg(&input_len[b])) return; // dead row

    const float* __restrict__ x = acts + (size_t)row * V_DIM;
    const int tid = threadIdx.x;

    const float4* __restrict__ x4 = reinterpret_cast<const float4*>(x);
    float s = 0.0f;
    #pragma unroll
    for (int k = 0; k < 4; ++k) {
        float4 r = __ldcs(&x4[tid + 256 * k]);   // stream, evict-first
        s += ex2(r.x * LOG2E) + ex2(r.y * LOG2E)
           + ex2(r.z * LOG2E) + ex2(r.w * LOG2E);
    }

    __shared__ float s_s[8];
    __shared__ float s_bcast;
    #pragma unroll
    for (int o = 16; o; o >>= 1) s += __shfl_xor_sync(0xffffffffu, s, o);
    if ((tid & 31) == 0) s_s[tid >> 5] = s;
    __syncthreads();
    if (tid < 32) {
        float v = (tid < 8) ? s_s[tid] : 0.0f;
        #pragma unroll
        for (int o = 4; o; o >>= 1) v += __shfl_xor_sync(0xffffffffu, v, o);
        if (tid == 0) s_bcast = lg2(v);
    }
    __syncthreads();
    const float log2sum = s_bcast;

    if (tid < 64) {
        const int cls = __ldg(&labels[b * S_DIM + tid]);
        g_pr[((size_t)b * T_DIM + t) * 64 + tid] =
            ex2(x[cls] * LOG2E - log2sum + PRESCALE);
    }
    if (tid == 64)
        g_pb[(size_t)b * T_DIM + t] = ex2(x[0] * LOG2E - log2sum + PRESCALE);
}

// ---------------------------------------------------------------------------
// Kernel 2: scaled linear-domain CTC alpha, one block per batch.
// 512-thread preload (16 warps of MLP); warp 0 runs the recursion.
// Renorm (period 8, deferred redux) is folded into the NEXT step's prob
// registers -> zero multiplies of live state on the chain.
// Last block reduces the 32 NLLs into out[0].
// ---------------------------------------------------------------------------
__global__ __launch_bounds__(512) void k_alpha(
    const int* __restrict__ labels,
    const int* __restrict__ input_len,
    const int* __restrict__ target_len,
    float* __restrict__ out) {
    extern __shared__ float sm[];
    float*  s_pb = sm;                               // 520 floats (pad)
    float2* s_pr = reinterpret_cast<float2*>(sm + 520);  // (T+4)*32 float2
    const int b   = blockIdx.x;
    const int tid = threadIdx.x;
    const int len = __ldg(&input_len[b]);

    // Cooperative preload of live rows (16 warps -> high MLP).
    {
        const float4* __restrict__ srcb =
            reinterpret_cast<const float4*>(g_pb + (size_t)b * T_DIM);
        float4* dstb = reinterpret_cast<float4*>(s_pb);
        for (int i = tid; i < (len + 3) >> 2; i += 512) dstb[i] = srcb[i];
        const float4* __restrict__ srcp =
            reinterpret_cast<const float4*>(g_pr + (size_t)b * T_DIM * 64);
        float4* dstp = reinterpret_cast<float4*>(s_pr);
        const int n4 = len * 16;                     // 64 floats/row / 4
        #pragma unroll 4
        for (int i = tid; i < n4; i += 512) dstp[i] = srcp[i];
    }
    __syncthreads();

    if (tid < 32) {
        const int lane = tid;
        const int* lab = labels + b * S_DIM;
        const float m0   = (lane == 0) ? 0.0f : 1.0f;
        const float sk1f = ((lane >= 1) &&
            (__ldg(&lab[2 * lane]) != __ldg(&lab[2 * lane - 1]))) ? 1.0f : 0.0f;
        const float sk3f =
            (__ldg(&lab[2 * lane + 1]) != __ldg(&lab[2 * lane])) ? 1.0f : 0.0f;

        const float2* __restrict__ prl = s_pr + lane;    // lane's pair column

        float a0 = (lane == 0) ? s_pb[0] : 0.0f;
        float a1 = (lane == 0) ? prl[0].x : 0.0f;
        float a2 = 0.0f, a3 = 0.0f, a4 = 0.0f;
        float p3 = 0.0f;
        float s01 = a0 + a1;
        float s23 = 0.0f;
        int   E  = 0;

        auto step = [&](float pb, float2 pr) {
            const float n3 = fmaf(a1, sk3f, s23) * pr.y;
            const float t3 = __shfl_up_sync(0xffffffffu, n3, 1);
            const float n0 = fmaf(p3, m0, a0) * pb;
            const float n1 = fmaf(p3, sk1f, s01) * pr.x;
            const float n2 = (a2 + a1) * pb;
            a4 = (a4 + a3) * pb;          // real only on lane31; junk benign
            s01 = n0 + n1;
            s23 = n2 + n3;
            a0 = n0; a1 = n1; a2 = n2; a3 = n3;
            p3 = t3;                      // lane0 junk masked by m0/sk1f
        };

        const int nsteps = len - 1;
        const int ngr    = nsteps >> 3;              // groups of 8 steps
        int t = 1;

        // 2-row named-register prefetch pipeline.
        float  pb0 = s_pb[1],        pb1 = s_pb[2];
        float2 pr0 = prl[1 * 32],    pr1 = prl[2 * 32];

        unsigned pend = 0x3f800000u;                 // bits(1.0f): identity
        #pragma unroll 1
        for (int g = 0; g < ngr; ++g) {
            // Apply pending renorm by scaling the NEXT step's prob registers
            // (off-chain; equivalent to scaling all alphas).
            const int e = (int)(pend >> 23);
            E += e - 127;
            const float sc = __uint_as_float((unsigned)(254 - e) << 23);
            pb0 *= sc; pr0.x *= sc; pr0.y *= sc;

            #pragma unroll
            for (int u = 0; u < 4; ++u) {            // 4 units x 2 steps
                const float  npb0 = s_pb[t + 2],       npb1 = s_pb[t + 3];
                const float2 npr0 = prl[(t + 2) * 32], npr1 = prl[(t + 3) * 32];
                step(pb0, pr0);
                step(pb1, pr1);
                pb0 = npb0; pr0 = npr0;
                pb1 = npb1; pr1 = npr1;
                t += 2;
            }
            // Issue redux now; consumed at the top of the next group.
            float m = fmaxf(fmaxf(a0, a1), fmaxf(fmaxf(a2, a3), a4));
            pend = warp_max_u32(__float_as_uint(m));
        }
        #pragma unroll 1
        for (; t < len; ++t)                          // <=7 tail steps
            step(s_pb[t], prl[t * 32]);
        // (pending redux intentionally dropped: E only counts applied scales)

        // Stash alphas in smem (slab no longer needed) and finalize.
        __syncwarp();
        s_pb[4 * lane + 0] = a0;
        s_pb[4 * lane + 1] = a1;
        s_pb[4 * lane + 2] = a2;
        s_pb[4 * lane + 3] = a3;
        if (lane == 31) s_pb[128] = a4;
        __syncwarp();

        if (lane == 0) {
            int hi = 2 * __ldg(&target_len[b]);
            if (hi > L_DIM - 1) hi = L_DIM - 1;
            int lo = hi - 1; if (lo < 0) lo = 0;
            const float sum = s_pb[hi] + s_pb[lo];
            float v = -(lg2(sum) + (float)E - PRESCALE * (float)len) * LN2;
            if (!isfinite(v) || v > 1e29f || sum <= 0.0f) v = 0.0f;
            g_nll[b] = v;

            __threadfence();
            const int old = atomicAdd(&g_done, 1);
            if (old == B_DIM - 1) {
                __threadfence();
                float s = 0.0f;
                #pragma unroll
                for (int i = 0; i < B_DIM; ++i)
                    s += ((volatile float*)g_nll)[i];
                out[0] = s;
                g_done = 0;
            }
        }
    }
}

extern "C" void kernel_launch(void* const* d_in, const int* in_sizes, int n_in,
                              void* d_out, int out_size) {
    const float* acts   = (const float*)d_in[0];
    const int*   labels = (const int*)d_in[1];
    const int*   ilen   = (const int*)d_in[2];
    const int*   tlen   = (const int*)d_in[3];
    (void)in_sizes; (void)n_in; (void)out_size;

    // s_pb: 520 floats; s_pr: (T+4) rows x 32 float2 (prefetch slack).
    const int smem_bytes = (520 + (T_DIM + 4) * 64) * (int)sizeof(float);
    cudaFuncSetAttribute(k_alpha, cudaFuncAttributeMaxDynamicSharedMemorySize,
                         smem_bytes);

    k_lse_gather<<<T_DIM * B_DIM, 256>>>(acts, labels, ilen);
    k_alpha<<<B_DIM, 512, smem_bytes>>>(labels, ilen, tlen, (float*)d_out);
}